// round 14
// baseline (speedup 1.0000x reference)
#include <cuda_runtime.h>
#include <cuda_bf16.h>
#include <math.h>

#define HW     128
#define NPIX   (HW*HW)        // 16384
#define BSZ    128
#define NPACK  128            // packed complex images
#define PITCHF 129            // smem row pitch in floats
#define GK     256            // GEMM K-splits (chunk = 64)
#define NGRP   32             // psd reduction image groups (4 images each)

// ---------------- device scratch ----------------
__device__ float          g_norm[2*BSZ];
__device__ float          g_dot_part[GK*BSZ*BSZ]; // 16 MB partial dots (L2-resident)
__device__ float          g_dist[BSZ*BSZ];
__device__ float          g_lse[BSZ];
__device__ __nv_bfloat16  g_psd[NPACK*NPIX];      // per packed-image |Z|^2 (4 MB, bf16)
__device__ float          g_S[NGRP*NPIX];         // image-group partial sums (2 MB)
__device__ double         g_red_log[128];
__device__ double         g_red_avg[128];

// ---------------- f32x2 packed helpers ----------------
__device__ __forceinline__ unsigned long long pk2(float x){
    unsigned long long r; asm("mov.b64 %0, {%1, %1};" : "=l"(r) : "f"(x)); return r;
}
__device__ __forceinline__ void upk2(unsigned long long v, float& lo, float& hi){
    asm("mov.b64 {%0, %1}, %2;" : "=f"(lo), "=f"(hi) : "l"(v));
}
__device__ __forceinline__ void ffma2(unsigned long long& c, unsigned long long a, unsigned long long b){
    asm("fma.rn.f32x2 %0, %1, %2, %3;" : "=l"(c) : "l"(a), "l"(b), "l"(c));
}

// ---------------- FFT register helpers ----------------
__device__ __forceinline__ void cmul_ip(float& vr, float& vi, float2 w){
    float t = vr;
    vr = vr*w.x - vi*w.y;
    vi = t*w.y + vi*w.x;
}
__device__ __forceinline__ void bf4(float&x0r,float&x0i,float&x1r,float&x1i,
                                    float&x2r,float&x2i,float&x3r,float&x3i){
    float t0r=x0r+x2r, t0i=x0i+x2i, t1r=x0r-x2r, t1i=x0i-x2i;
    float t2r=x1r+x3r, t2i=x1i+x3i, t3r=x1r-x3r, t3i=x1i-x3i;
    x0r=t0r+t2r; x0i=t0i+t2i;
    x1r=t1r+t3i; x1i=t1i-t3r;     // t1 + (-i)*t3
    x2r=t0r-t2r; x2i=t0i-t2i;
    x3r=t1r-t3i; x3i=t1i+t3r;     // t1 + (+i)*t3
}

// 16-pt DFT (DIF radix-4 x radix-4). Natural in; slot (4e1+e2) holds d = e1+4e2.
__device__ __forceinline__ void fft16(float* xr, float* xi, const float2* tw){
#pragma unroll
    for (int s0 = 0; s0 < 4; s0++){
        bf4(xr[s0],xi[s0], xr[s0+4],xi[s0+4], xr[s0+8],xi[s0+8], xr[s0+12],xi[s0+12]);
        if (s0){
            cmul_ip(xr[s0+4],  xi[s0+4],  tw[8*s0]);
            cmul_ip(xr[s0+8],  xi[s0+8],  tw[16*s0]);
            cmul_ip(xr[s0+12], xi[s0+12], tw[24*s0]);
        }
    }
#pragma unroll
    for (int e1 = 0; e1 < 4; e1++)
        bf4(xr[4*e1],xi[4*e1], xr[4*e1+1],xi[4*e1+1],
            xr[4*e1+2],xi[4*e1+2], xr[4*e1+3],xi[4*e1+3]);
}

// 8-pt DFT (DIF radix-2 x radix-4). Natural in; slot (4f1+f2) holds k' = f1+2f2.
__device__ __forceinline__ void fft8(float* yr, float* yi, const float2* tw){
#pragma unroll
    for (int n2 = 0; n2 < 4; n2++){
        float ur=yr[n2], ui=yi[n2], vr=yr[n2+4], vi=yi[n2+4];
        yr[n2]=ur+vr; yi[n2]=ui+vi;
        float dr=ur-vr, di=ui-vi;
        if (n2 == 0){ yr[n2+4]=dr; yi[n2+4]=di; }
        else {
            float2 w = tw[16*n2];                       // W8^{n2}
            yr[n2+4]=dr*w.x-di*w.y; yi[n2+4]=dr*w.y+di*w.x;
        }
    }
    bf4(yr[0],yi[0], yr[1],yi[1], yr[2],yi[2], yr[3],yi[3]);
    bf4(yr[4],yi[4], yr[5],yi[5], yr[6],yi[6], yr[7],yi[7]);
}

// stored index p = 8*d1 + k'  ->  frequency k = d1 + 16*k'
__device__ __forceinline__ int sig2(int p){ return (p>>3) | ((p&7)<<4); }
__device__ __forceinline__ int isig2(int k){ return ((k&15)<<3) | (k>>4); }
__device__ __forceinline__ int tau2(int p){ return isig2((128 - sig2(p)) & 127); }

// ---------------- GEMM: dot(a_i, b_j), f32x2 packed, K-split 256 ----------------
__global__ __launch_bounds__(256) void dot_kernel(const float* __restrict__ A, const float* __restrict__ B) {
    __shared__ __align__(16) float As[16][132];
    __shared__ __align__(16) float Bs[16][68];
    int tid = threadIdx.x;
    int tx = tid & 15, ty = tid >> 4;
    int nb = blockIdx.x * 64;
    int k0 = blockIdx.z * 64;

    unsigned long long acc[4][4];
#pragma unroll
    for (int rp = 0; rp < 4; rp++)
#pragma unroll
        for (int c = 0; c < 4; c++) acc[rp][c] = 0ull;

#pragma unroll
    for (int ks = 0; ks < 4; ks++) {
        int kb = k0 + ks * 16;
        __syncthreads();
#pragma unroll
        for (int i = 0; i < 2; i++) {
            int idx = tid + i * 256;
            int row = idx >> 2, kq = idx & 3;
            float4 v = *reinterpret_cast<const float4*>(A + (size_t)row * NPIX + kb + kq * 4);
            As[kq*4+0][row] = v.x; As[kq*4+1][row] = v.y;
            As[kq*4+2][row] = v.z; As[kq*4+3][row] = v.w;
        }
        {
            int row = tid >> 2, kq = tid & 3;
            float4 v = *reinterpret_cast<const float4*>(B + (size_t)(nb + row) * NPIX + kb + kq * 4);
            Bs[kq*4+0][row] = v.x; Bs[kq*4+1][row] = v.y;
            Bs[kq*4+2][row] = v.z; Bs[kq*4+3][row] = v.w;
        }
        __syncthreads();
#pragma unroll
        for (int kk = 0; kk < 16; kk++) {
            const double2* ap = reinterpret_cast<const double2*>(&As[kk][ty*8]);
            double2 a01 = ap[0], a23 = ap[1];
            unsigned long long a2[4];
            a2[0] = __double_as_longlong(a01.x);
            a2[1] = __double_as_longlong(a01.y);
            a2[2] = __double_as_longlong(a23.x);
            a2[3] = __double_as_longlong(a23.y);
            float4 b0 = *reinterpret_cast<const float4*>(&Bs[kk][tx*4]);
            unsigned long long b2[4];
            b2[0] = pk2(b0.x); b2[1] = pk2(b0.y); b2[2] = pk2(b0.z); b2[3] = pk2(b0.w);
#pragma unroll
            for (int rp = 0; rp < 4; rp++)
#pragma unroll
                for (int c = 0; c < 4; c++) ffma2(acc[rp][c], a2[rp], b2[c]);
        }
    }
    float* outp = g_dot_part + (size_t)blockIdx.z * BSZ * BSZ;
#pragma unroll
    for (int rp = 0; rp < 4; rp++) {
        float lo0, hi0, lo1, hi1, lo2, hi2, lo3, hi3;
        upk2(acc[rp][0], lo0, hi0); upk2(acc[rp][1], lo1, hi1);
        upk2(acc[rp][2], lo2, hi2); upk2(acc[rp][3], lo3, hi3);
        *reinterpret_cast<float4*>(outp + (ty*8 + 2*rp    ) * BSZ + nb + tx*4) = make_float4(lo0, lo1, lo2, lo3);
        *reinterpret_cast<float4*>(outp + (ty*8 + 2*rp + 1) * BSZ + nb + tx*4) = make_float4(hi0, hi1, hi2, hi3);
    }
}

// ---------------- Dist + per-row logsumexp (512 threads, 4x64 K partials) ----------------
__global__ __launch_bounds__(512) void dist_lse_kernel() {
    int i = blockIdx.x;
    int tid = threadIdx.x;
    int j = tid & 127, part = tid >> 7;            // part in [0,4)
    float dp = 0.f;
#pragma unroll 16
    for (int s = part*64; s < part*64 + 64; s++)
        dp += g_dot_part[(size_t)s*BSZ*BSZ + i*BSZ + j];
    __shared__ float p4[4][BSZ];
    __shared__ float red[BSZ];
    p4[part][j] = dp;
    __syncthreads();

    float d = 0.f;
    if (part == 0) {
        float dot = (p4[0][j] + p4[1][j]) + (p4[2][j] + p4[3][j]);
        float d2 = g_norm[i] + g_norm[BSZ + j] - 2.f * dot;
        d = sqrtf(fmaxf(d2, 0.f));
        g_dist[i*BSZ + j] = d;
        red[j] = d;
    }
    __syncthreads();
    for (int off = 64; off > 0; off >>= 1) {
        if (tid < off) red[tid] = fmaxf(red[tid], red[tid + off]);
        __syncthreads();
    }
    float mx = red[0];
    __syncthreads();
    if (part == 0) red[j] = expf(d - mx);
    __syncthreads();
    for (int off = 64; off > 0; off >>= 1) {
        if (tid < off) red[tid] += red[tid + off];
        __syncthreads();
    }
    if (tid == 0) g_lse[i] = mx + logf(red[0]);
}

// ---------------- packed 2D FFT: register radix-16x8, 512 threads ----------------
__global__ __launch_bounds__(512, 1) void fft_psd_kernel(const float* __restrict__ x1, const float* __restrict__ x2) {
    extern __shared__ float sm[];
    float* SRe = sm;                               // [128][PITCHF]
    float* SIm = sm + 128*PITCHF;
    __shared__ float2 tw[128];
    __shared__ float nb1[16], nb2[16];
    int b = blockIdx.x;
    const float* sa = x1 + (size_t)b*NPIX;
    const float* sb = x2 + (size_t)b*NPIX;
    int tid = threadIdx.x;

    if (tid < 128) {
        float sn, cs;
        sincospif((float)tid / 64.f, &sn, &cs);
        tw[tid] = make_float2(cs, -sn);            // W128^tid
    }
    __syncthreads();                               // tw visible to ALL warps

    // ===== phase 1: rows, 16-pt stage (gmem -> regs -> smem skewed) + norms =====
    float s1 = 0.f, s2 = 0.f;
#pragma unroll
    for (int h = 0; h < 2; h++) {
        int item = tid + 512*h;
        int r = item >> 3, n = item & 7;
        float xr[16], xi[16];
#pragma unroll
        for (int s = 0; s < 16; s++) {
            float a  = sa[r*128 + n + 8*s];
            float bb = sb[r*128 + n + 8*s];
            xr[s] = a; xi[s] = bb;
            s1 += a*a; s2 += bb*bb;
        }
        fft16(xr, xi, tw);
#pragma unroll
        for (int sl = 0; sl < 16; sl++) {
            int e1 = sl >> 2, e2 = sl & 3;
            int d = e1 + 4*e2;
            float vr = xr[sl], vi = xi[sl];
            if (d) cmul_ip(vr, vi, tw[n*d]);
            int col = 8*((d + r) & 15) + n;
            SRe[r*PITCHF + col] = vr;
            SIm[r*PITCHF + col] = vi;
        }
    }
#pragma unroll
    for (int o = 16; o; o >>= 1) {
        s1 += __shfl_down_sync(0xffffffffu, s1, o);
        s2 += __shfl_down_sync(0xffffffffu, s2, o);
    }
    if ((tid & 31) == 0) { nb1[tid>>5] = s1; nb2[tid>>5] = s2; }
    __syncthreads();                               // phase-1 smem writes + nb staged
    if (tid < 16) {
        float a = nb1[tid], c = nb2[tid];
#pragma unroll
        for (int o = 8; o; o >>= 1) {
            a += __shfl_down_sync(0xffffu, a, o);
            c += __shfl_down_sync(0xffffu, c, o);
        }
        if (tid == 0) { g_norm[b] = a; g_norm[b + BSZ] = c; }
    }

    // ===== phase 2: rows, 8-pt stage; two row-halves, staged reads =====
#pragma unroll
    for (int half = 0; half < 2; half++) {
        float yr[2][8], yi[2][8];
#pragma unroll
        for (int u = 0; u < 2; u++) {
            int i = tid + 512*u;
            int row = half*64 + (i & 63);
            int d1 = i >> 6;
            int cb = row*PITCHF + 8*((d1 + row) & 15);
#pragma unroll
            for (int k = 0; k < 8; k++) { yr[u][k] = SRe[cb+k]; yi[u][k] = SIm[cb+k]; }
        }
        __syncthreads();                           // all reads done before writes
#pragma unroll
        for (int u = 0; u < 2; u++) {
            int i = tid + 512*u;
            int row = half*64 + (i & 63);
            int d1 = i >> 6;
            fft8(yr[u], yi[u], tw);
            int ob = row*PITCHF + 8*d1;
#pragma unroll
            for (int f2 = 0; f2 < 4; f2++) {
                SRe[ob + 2*f2]     = yr[u][f2];     // k' = 2*f2
                SIm[ob + 2*f2]     = yi[u][f2];
                SRe[ob + 2*f2 + 1] = yr[u][4+f2];   // k' = 1 + 2*f2
                SIm[ob + 2*f2 + 1] = yi[u][4+f2];
            }
        }
        __syncthreads();
    }

    // ===== phase 3: cols, 16-pt stage (in-place per thread; residue-disjoint) =====
#pragma unroll
    for (int u = 0; u < 2; u++) {
        int item = tid + 512*u;
        int c = item & 127, n3 = (item >> 7) & 7;
        float zr[16], zi[16];
#pragma unroll
        for (int s = 0; s < 16; s++) {
            int m = n3 + 8*s;
            zr[s] = SRe[m*PITCHF + c];
            zi[s] = SIm[m*PITCHF + c];
        }
        fft16(zr, zi, tw);
#pragma unroll
        for (int sl = 0; sl < 16; sl++) {
            int e1 = sl >> 2, e2 = sl & 3;
            int d = e1 + 4*e2;
            float vr = zr[sl], vi = zi[sl];
            if (d) cmul_ip(vr, vi, tw[n3*d]);
            SRe[(8*d + n3)*PITCHF + c] = vr;
            SIm[(8*d + n3)*PITCHF + c] = vi;
        }
    }
    __syncthreads();

    // ===== phase 4: cols, 8-pt stage + |Z|^2 (bf16) -> gmem =====
#pragma unroll
    for (int u = 0; u < 4; u++) {
        int item = tid + 512*u;
        int c4 = item & 127, d1 = item >> 7;       // d1 in [0,16)
        float wr[8], wi[8];
#pragma unroll
        for (int k = 0; k < 8; k++) {
            wr[k] = SRe[(8*d1 + k)*PITCHF + c4];
            wi[k] = SIm[(8*d1 + k)*PITCHF + c4];
        }
        fft8(wr, wi, tw);
        __nv_bfloat16* dst = g_psd + (size_t)b*NPIX + c4;
#pragma unroll
        for (int f2 = 0; f2 < 4; f2++) {
            dst[(8*d1 + 2*f2    )*128] = __float2bfloat16_rn(wr[f2]*wr[f2] + wi[f2]*wi[f2]);
            dst[(8*d1 + 2*f2 + 1)*128] = __float2bfloat16_rn(wr[4+f2]*wr[4+f2] + wi[4+f2]*wi[4+f2]);
        }
    }
}

// ---------------- S partials: 32 groups x 4 images, uint4 (8 bf16) loads ----------------
__global__ __launch_bounds__(256) void psd_reduce_kernel() {
    int t = blockIdx.x * 256 + threadIdx.x;        // oct index 0..2047
    int imgbase = blockIdx.y * 4;
    const uint4* src = reinterpret_cast<const uint4*>(g_psd);
    float s[8];
#pragma unroll
    for (int e = 0; e < 8; e++) s[e] = 0.f;
#pragma unroll
    for (int i = 0; i < 4; i++) {
        uint4 v = src[(size_t)(imgbase + i)*(NPIX/8) + t];
        unsigned w[4] = {v.x, v.y, v.z, v.w};
#pragma unroll
        for (int h = 0; h < 4; h++) {
            float2 p = __bfloat1622float2(*reinterpret_cast<const __nv_bfloat162*>(&w[h]));
            s[2*h]   += p.x;
            s[2*h+1] += p.y;
        }
    }
    float4* dst = reinterpret_cast<float4*>(g_S + (size_t)blockIdx.y*NPIX + t*8);
    dst[0] = make_float4(s[0], s[1], s[2], s[3]);
    dst[1] = make_float4(s[4], s[5], s[6], s[7]);
}

// ---------------- per-bin avgpsd via -k pairing (tau2), float log ----------------
__global__ void psd_stats_kernel() {
    int p = blockIdx.x * 128 + threadIdx.x;
    int pr = p >> 7, pc = p & 127;
    int q = tau2(pr) * 128 + tau2(pc);
    double Sp = 0.0, Sq = 0.0;
#pragma unroll
    for (int h = 0; h < NGRP; h++) { Sp += (double)g_S[h*NPIX + p]; Sq += (double)g_S[h*NPIX + q]; }
    double avg = (Sp + Sq) * (1.0 / 512.0);
    __shared__ double shl[128];
    __shared__ double sha[128];
    shl[threadIdx.x] = (double)logf((float)avg);
    sha[threadIdx.x] = avg;
    __syncthreads();
    for (int off = 64; off > 0; off >>= 1) {
        if (threadIdx.x < off) {
            shl[threadIdx.x] += shl[threadIdx.x + off];
            sha[threadIdx.x] += sha[threadIdx.x + off];
        }
        __syncthreads();
    }
    if (threadIdx.x == 0) { g_red_log[blockIdx.x] = shl[0]; g_red_avg[blockIdx.x] = sha[0]; }
}

// ---------------- final scalar ----------------
__global__ void final_kernel(float* __restrict__ out) {
    __shared__ double sh[128];
    int t = threadIdx.x;

    sh[t] = (double)(g_lse[t] - g_dist[t*BSZ + t]);
    __syncthreads();
    for (int off = 64; off > 0; off >>= 1) {
        if (t < off) sh[t] += sh[t + off];
        __syncthreads();
    }
    double ce = sh[0] / (double)BSZ;
    __syncthreads();

    sh[t] = g_red_log[t]; __syncthreads();
    for (int off = 64; off > 0; off >>= 1) {
        if (t < off) sh[t] += sh[t + off];
        __syncthreads();
    }
    double slog = sh[0];
    __syncthreads();

    sh[t] = g_red_avg[t]; __syncthreads();
    for (int off = 64; off > 0; off >>= 1) {
        if (t < off) sh[t] += sh[t + off];
        __syncthreads();
    }
    double savg = sh[0];

    if (t == 0) {
        double r = slog / (double)NPIX - log(savg / (double)NPIX);
        out[0] = (float)(ce - 0.1 * r);
    }
}

// ---------------- launch: fork/join overlap of dot (s2) with fft chain ----------------
// Graph DAG: fork -> { s2: dot } || { main: fft -> reduce -> stats } -> join ->
//            dist_lse -> final. Stream/event objects are created per call (a
//            handful of calls total: correctness + capture); identical work
//            every call, graph-capture-legal host ops.
extern "C" void kernel_launch(void* const* d_in, const int* in_sizes, int n_in,
                              void* d_out, int out_size) {
    const float* x1 = (const float*)d_in[0];
    const float* x2 = (const float*)d_in[1];
    float* out = (float*)d_out;

    const int smem = 2 * 128 * PITCHF * (int)sizeof(float);   // 132096 B
    cudaFuncSetAttribute(fft_psd_kernel, cudaFuncAttributeMaxDynamicSharedMemorySize, smem);

    cudaStream_t s2;
    cudaEvent_t evFork, evJoin;
    cudaStreamCreateWithFlags(&s2, cudaStreamNonBlocking);
    cudaEventCreateWithFlags(&evFork, cudaEventDisableTiming);
    cudaEventCreateWithFlags(&evJoin, cudaEventDisableTiming);

    // fork: s2 branches off the capture-origin stream
    cudaEventRecord(evFork, 0);
    cudaStreamWaitEvent(s2, evFork, 0);

    // branch A (s2): the GEMM
    dot_kernel<<<dim3(2, 1, GK), 256, 0, s2>>>(x1, x2);
    cudaEventRecord(evJoin, s2);

    // branch B (main): FFT chain
    fft_psd_kernel<<<NPACK, 512, smem>>>(x1, x2);
    psd_reduce_kernel<<<dim3(8, NGRP), 256>>>();
    psd_stats_kernel<<<128, 128>>>();

    // join: dist_lse needs dot partials + fft norms
    cudaStreamWaitEvent(0, evJoin, 0);
    dist_lse_kernel<<<BSZ, 512>>>();
    final_kernel<<<1, 128>>>(out);
}

// round 15
// speedup vs baseline: 1.1008x; 1.1008x over previous
#include <cuda_runtime.h>
#include <cuda_bf16.h>
#include <math.h>

#define HW     128
#define NPIX   (HW*HW)        // 16384
#define BSZ    128
#define NPACK  128            // packed complex images
#define PITCHF 129            // smem row pitch in floats
#define GK     256            // GEMM K-splits (chunk = 64)
#define NGRP   8              // psd reduction image groups (16 images each)

// ---------------- device scratch ----------------
__device__ float          g_norm[2*BSZ];
__device__ float          g_dot_part[GK*BSZ*BSZ]; // 16 MB partial dots (L2-resident)
__device__ float          g_dist[BSZ*BSZ];
__device__ float          g_lse[BSZ];
__device__ __nv_bfloat16  g_psd[NPACK*NPIX];      // per packed-image |Z|^2 (4 MB, bf16)
__device__ float          g_S[NGRP*NPIX];         // image-group partial sums (512 KB)
__device__ double         g_red_log[128];
__device__ double         g_red_avg[128];

// ---------------- f32x2 packed helpers ----------------
__device__ __forceinline__ unsigned long long pk2(float x){
    unsigned long long r; asm("mov.b64 %0, {%1, %1};" : "=l"(r) : "f"(x)); return r;
}
__device__ __forceinline__ void upk2(unsigned long long v, float& lo, float& hi){
    asm("mov.b64 {%0, %1}, %2;" : "=f"(lo), "=f"(hi) : "l"(v));
}
__device__ __forceinline__ void ffma2(unsigned long long& c, unsigned long long a, unsigned long long b){
    asm("fma.rn.f32x2 %0, %1, %2, %3;" : "=l"(c) : "l"(a), "l"(b), "l"(c));
}

// ---------------- FFT register helpers ----------------
__device__ __forceinline__ void cmul_ip(float& vr, float& vi, float2 w){
    float t = vr;
    vr = vr*w.x - vi*w.y;
    vi = t*w.y + vi*w.x;
}
__device__ __forceinline__ void bf4(float&x0r,float&x0i,float&x1r,float&x1i,
                                    float&x2r,float&x2i,float&x3r,float&x3i){
    float t0r=x0r+x2r, t0i=x0i+x2i, t1r=x0r-x2r, t1i=x0i-x2i;
    float t2r=x1r+x3r, t2i=x1i+x3i, t3r=x1r-x3r, t3i=x1i-x3i;
    x0r=t0r+t2r; x0i=t0i+t2i;
    x1r=t1r+t3i; x1i=t1i-t3r;     // t1 + (-i)*t3
    x2r=t0r-t2r; x2i=t0i-t2i;
    x3r=t1r-t3i; x3i=t1i+t3r;     // t1 + (+i)*t3
}

// 16-pt DFT (DIF radix-4 x radix-4). Natural in; slot (4e1+e2) holds d = e1+4e2.
__device__ __forceinline__ void fft16(float* xr, float* xi, const float2* tw){
#pragma unroll
    for (int s0 = 0; s0 < 4; s0++){
        bf4(xr[s0],xi[s0], xr[s0+4],xi[s0+4], xr[s0+8],xi[s0+8], xr[s0+12],xi[s0+12]);
        if (s0){
            cmul_ip(xr[s0+4],  xi[s0+4],  tw[8*s0]);
            cmul_ip(xr[s0+8],  xi[s0+8],  tw[16*s0]);
            cmul_ip(xr[s0+12], xi[s0+12], tw[24*s0]);
        }
    }
#pragma unroll
    for (int e1 = 0; e1 < 4; e1++)
        bf4(xr[4*e1],xi[4*e1], xr[4*e1+1],xi[4*e1+1],
            xr[4*e1+2],xi[4*e1+2], xr[4*e1+3],xi[4*e1+3]);
}

// 8-pt DFT (DIF radix-2 x radix-4). Natural in; slot (4f1+f2) holds k' = f1+2f2.
__device__ __forceinline__ void fft8(float* yr, float* yi, const float2* tw){
#pragma unroll
    for (int n2 = 0; n2 < 4; n2++){
        float ur=yr[n2], ui=yi[n2], vr=yr[n2+4], vi=yi[n2+4];
        yr[n2]=ur+vr; yi[n2]=ui+vi;
        float dr=ur-vr, di=ui-vi;
        if (n2 == 0){ yr[n2+4]=dr; yi[n2+4]=di; }
        else {
            float2 w = tw[16*n2];                       // W8^{n2}
            yr[n2+4]=dr*w.x-di*w.y; yi[n2+4]=dr*w.y+di*w.x;
        }
    }
    bf4(yr[0],yi[0], yr[1],yi[1], yr[2],yi[2], yr[3],yi[3]);
    bf4(yr[4],yi[4], yr[5],yi[5], yr[6],yi[6], yr[7],yi[7]);
}

// stored index p = 8*d1 + k'  ->  frequency k = d1 + 16*k'
__device__ __forceinline__ int sig2(int p){ return (p>>3) | ((p&7)<<4); }
__device__ __forceinline__ int isig2(int k){ return ((k&15)<<3) | (k>>4); }
__device__ __forceinline__ int tau2(int p){ return isig2((128 - sig2(p)) & 127); }

// ---------------- GEMM: dot(a_i, b_j), f32x2 packed, K-split 256 ----------------
__global__ __launch_bounds__(256) void dot_kernel(const float* __restrict__ A, const float* __restrict__ B) {
    __shared__ __align__(16) float As[16][132];
    __shared__ __align__(16) float Bs[16][68];
    int tid = threadIdx.x;
    int tx = tid & 15, ty = tid >> 4;
    int nb = blockIdx.x * 64;
    int k0 = blockIdx.z * 64;

    unsigned long long acc[4][4];
#pragma unroll
    for (int rp = 0; rp < 4; rp++)
#pragma unroll
        for (int c = 0; c < 4; c++) acc[rp][c] = 0ull;

#pragma unroll
    for (int ks = 0; ks < 4; ks++) {
        int kb = k0 + ks * 16;
        __syncthreads();
#pragma unroll
        for (int i = 0; i < 2; i++) {
            int idx = tid + i * 256;
            int row = idx >> 2, kq = idx & 3;
            float4 v = *reinterpret_cast<const float4*>(A + (size_t)row * NPIX + kb + kq * 4);
            As[kq*4+0][row] = v.x; As[kq*4+1][row] = v.y;
            As[kq*4+2][row] = v.z; As[kq*4+3][row] = v.w;
        }
        {
            int row = tid >> 2, kq = tid & 3;
            float4 v = *reinterpret_cast<const float4*>(B + (size_t)(nb + row) * NPIX + kb + kq * 4);
            Bs[kq*4+0][row] = v.x; Bs[kq*4+1][row] = v.y;
            Bs[kq*4+2][row] = v.z; Bs[kq*4+3][row] = v.w;
        }
        __syncthreads();
#pragma unroll
        for (int kk = 0; kk < 16; kk++) {
            const double2* ap = reinterpret_cast<const double2*>(&As[kk][ty*8]);
            double2 a01 = ap[0], a23 = ap[1];
            unsigned long long a2[4];
            a2[0] = __double_as_longlong(a01.x);
            a2[1] = __double_as_longlong(a01.y);
            a2[2] = __double_as_longlong(a23.x);
            a2[3] = __double_as_longlong(a23.y);
            float4 b0 = *reinterpret_cast<const float4*>(&Bs[kk][tx*4]);
            unsigned long long b2[4];
            b2[0] = pk2(b0.x); b2[1] = pk2(b0.y); b2[2] = pk2(b0.z); b2[3] = pk2(b0.w);
#pragma unroll
            for (int rp = 0; rp < 4; rp++)
#pragma unroll
                for (int c = 0; c < 4; c++) ffma2(acc[rp][c], a2[rp], b2[c]);
        }
    }
    float* outp = g_dot_part + (size_t)blockIdx.z * BSZ * BSZ;
#pragma unroll
    for (int rp = 0; rp < 4; rp++) {
        float lo0, hi0, lo1, hi1, lo2, hi2, lo3, hi3;
        upk2(acc[rp][0], lo0, hi0); upk2(acc[rp][1], lo1, hi1);
        upk2(acc[rp][2], lo2, hi2); upk2(acc[rp][3], lo3, hi3);
        *reinterpret_cast<float4*>(outp + (ty*8 + 2*rp    ) * BSZ + nb + tx*4) = make_float4(lo0, lo1, lo2, lo3);
        *reinterpret_cast<float4*>(outp + (ty*8 + 2*rp + 1) * BSZ + nb + tx*4) = make_float4(hi0, hi1, hi2, hi3);
    }
}

// ---------------- Dist + per-row logsumexp (512 threads, 4x64 K partials) ----------------
__global__ __launch_bounds__(512) void dist_lse_kernel() {
    int i = blockIdx.x;
    int tid = threadIdx.x;
    int j = tid & 127, part = tid >> 7;            // part in [0,4)
    float dp = 0.f;
#pragma unroll 16
    for (int s = part*64; s < part*64 + 64; s++)
        dp += g_dot_part[(size_t)s*BSZ*BSZ + i*BSZ + j];
    __shared__ float p4[4][BSZ];
    __shared__ float red[BSZ];
    p4[part][j] = dp;
    __syncthreads();

    float d = 0.f;
    if (part == 0) {
        float dot = (p4[0][j] + p4[1][j]) + (p4[2][j] + p4[3][j]);
        float d2 = g_norm[i] + g_norm[BSZ + j] - 2.f * dot;
        d = sqrtf(fmaxf(d2, 0.f));
        g_dist[i*BSZ + j] = d;
        red[j] = d;
    }
    __syncthreads();
    for (int off = 64; off > 0; off >>= 1) {
        if (tid < off) red[tid] = fmaxf(red[tid], red[tid + off]);
        __syncthreads();
    }
    float mx = red[0];
    __syncthreads();
    if (part == 0) red[j] = expf(d - mx);
    __syncthreads();
    for (int off = 64; off > 0; off >>= 1) {
        if (tid < off) red[tid] += red[tid + off];
        __syncthreads();
    }
    if (tid == 0) g_lse[i] = mx + logf(red[0]);
}

// ---------------- packed 2D FFT: register radix-16x8, 512 threads ----------------
__global__ __launch_bounds__(512, 1) void fft_psd_kernel(const float* __restrict__ x1, const float* __restrict__ x2) {
    extern __shared__ float sm[];
    float* SRe = sm;                               // [128][PITCHF]
    float* SIm = sm + 128*PITCHF;
    __shared__ float2 tw[128];
    __shared__ float nb1[16], nb2[16];
    int b = blockIdx.x;
    const float* sa = x1 + (size_t)b*NPIX;
    const float* sb = x2 + (size_t)b*NPIX;
    int tid = threadIdx.x;

    if (tid < 128) {
        float sn, cs;
        sincospif((float)tid / 64.f, &sn, &cs);
        tw[tid] = make_float2(cs, -sn);            // W128^tid
    }
    __syncthreads();                               // tw visible to ALL warps

    // ===== phase 1: rows, 16-pt stage (gmem -> regs -> smem skewed) + norms =====
    float s1 = 0.f, s2 = 0.f;
#pragma unroll
    for (int h = 0; h < 2; h++) {
        int item = tid + 512*h;
        int r = item >> 3, n = item & 7;
        float xr[16], xi[16];
#pragma unroll
        for (int s = 0; s < 16; s++) {
            float a  = sa[r*128 + n + 8*s];
            float bb = sb[r*128 + n + 8*s];
            xr[s] = a; xi[s] = bb;
            s1 += a*a; s2 += bb*bb;
        }
        fft16(xr, xi, tw);
#pragma unroll
        for (int sl = 0; sl < 16; sl++) {
            int e1 = sl >> 2, e2 = sl & 3;
            int d = e1 + 4*e2;
            float vr = xr[sl], vi = xi[sl];
            if (d) cmul_ip(vr, vi, tw[n*d]);
            int col = 8*((d + r) & 15) + n;
            SRe[r*PITCHF + col] = vr;
            SIm[r*PITCHF + col] = vi;
        }
    }
#pragma unroll
    for (int o = 16; o; o >>= 1) {
        s1 += __shfl_down_sync(0xffffffffu, s1, o);
        s2 += __shfl_down_sync(0xffffffffu, s2, o);
    }
    if ((tid & 31) == 0) { nb1[tid>>5] = s1; nb2[tid>>5] = s2; }
    __syncthreads();                               // phase-1 smem writes + nb staged
    if (tid < 16) {
        float a = nb1[tid], c = nb2[tid];
#pragma unroll
        for (int o = 8; o; o >>= 1) {
            a += __shfl_down_sync(0xffffu, a, o);
            c += __shfl_down_sync(0xffffu, c, o);
        }
        if (tid == 0) { g_norm[b] = a; g_norm[b + BSZ] = c; }
    }

    // ===== phase 2: rows, 8-pt stage; two row-halves, staged reads =====
#pragma unroll
    for (int half = 0; half < 2; half++) {
        float yr[2][8], yi[2][8];
#pragma unroll
        for (int u = 0; u < 2; u++) {
            int i = tid + 512*u;
            int row = half*64 + (i & 63);
            int d1 = i >> 6;
            int cb = row*PITCHF + 8*((d1 + row) & 15);
#pragma unroll
            for (int k = 0; k < 8; k++) { yr[u][k] = SRe[cb+k]; yi[u][k] = SIm[cb+k]; }
        }
        __syncthreads();                           // all reads done before writes
#pragma unroll
        for (int u = 0; u < 2; u++) {
            int i = tid + 512*u;
            int row = half*64 + (i & 63);
            int d1 = i >> 6;
            fft8(yr[u], yi[u], tw);
            int ob = row*PITCHF + 8*d1;
#pragma unroll
            for (int f2 = 0; f2 < 4; f2++) {
                SRe[ob + 2*f2]     = yr[u][f2];     // k' = 2*f2
                SIm[ob + 2*f2]     = yi[u][f2];
                SRe[ob + 2*f2 + 1] = yr[u][4+f2];   // k' = 1 + 2*f2
                SIm[ob + 2*f2 + 1] = yi[u][4+f2];
            }
        }
        __syncthreads();
    }

    // ===== phase 3: cols, 16-pt stage (in-place per thread; residue-disjoint) =====
#pragma unroll
    for (int u = 0; u < 2; u++) {
        int item = tid + 512*u;
        int c = item & 127, n3 = (item >> 7) & 7;
        float zr[16], zi[16];
#pragma unroll
        for (int s = 0; s < 16; s++) {
            int m = n3 + 8*s;
            zr[s] = SRe[m*PITCHF + c];
            zi[s] = SIm[m*PITCHF + c];
        }
        fft16(zr, zi, tw);
#pragma unroll
        for (int sl = 0; sl < 16; sl++) {
            int e1 = sl >> 2, e2 = sl & 3;
            int d = e1 + 4*e2;
            float vr = zr[sl], vi = zi[sl];
            if (d) cmul_ip(vr, vi, tw[n3*d]);
            SRe[(8*d + n3)*PITCHF + c] = vr;
            SIm[(8*d + n3)*PITCHF + c] = vi;
        }
    }
    __syncthreads();

    // ===== phase 4: cols, 8-pt stage + |Z|^2 (bf16) -> gmem =====
#pragma unroll
    for (int u = 0; u < 4; u++) {
        int item = tid + 512*u;
        int c4 = item & 127, d1 = item >> 7;       // d1 in [0,16)
        float wr[8], wi[8];
#pragma unroll
        for (int k = 0; k < 8; k++) {
            wr[k] = SRe[(8*d1 + k)*PITCHF + c4];
            wi[k] = SIm[(8*d1 + k)*PITCHF + c4];
        }
        fft8(wr, wi, tw);
        __nv_bfloat16* dst = g_psd + (size_t)b*NPIX + c4;
#pragma unroll
        for (int f2 = 0; f2 < 4; f2++) {
            dst[(8*d1 + 2*f2    )*128] = __float2bfloat16_rn(wr[f2]*wr[f2] + wi[f2]*wi[f2]);
            dst[(8*d1 + 2*f2 + 1)*128] = __float2bfloat16_rn(wr[4+f2]*wr[4+f2] + wi[4+f2]*wi[4+f2]);
        }
    }
}

// ---------------- S partials: 8 groups x 16 images, uint4 (8 bf16) loads ----------------
__global__ __launch_bounds__(256) void psd_reduce_kernel() {
    int t = blockIdx.x * 256 + threadIdx.x;        // oct index 0..2047
    int imgbase = blockIdx.y * 16;
    const uint4* src = reinterpret_cast<const uint4*>(g_psd);
    float s[8];
#pragma unroll
    for (int e = 0; e < 8; e++) s[e] = 0.f;
#pragma unroll
    for (int i = 0; i < 16; i++) {
        uint4 v = src[(size_t)(imgbase + i)*(NPIX/8) + t];
        unsigned w[4] = {v.x, v.y, v.z, v.w};
#pragma unroll
        for (int h = 0; h < 4; h++) {
            float2 p = __bfloat1622float2(*reinterpret_cast<const __nv_bfloat162*>(&w[h]));
            s[2*h]   += p.x;
            s[2*h+1] += p.y;
        }
    }
    float4* dst = reinterpret_cast<float4*>(g_S + (size_t)blockIdx.y*NPIX + t*8);
    dst[0] = make_float4(s[0], s[1], s[2], s[3]);
    dst[1] = make_float4(s[4], s[5], s[6], s[7]);
}

// ---------------- per-bin avgpsd via -k pairing (tau2), float log ----------------
__global__ void psd_stats_kernel() {
    int p = blockIdx.x * 128 + threadIdx.x;
    int pr = p >> 7, pc = p & 127;
    int q = tau2(pr) * 128 + tau2(pc);
    double Sp = 0.0, Sq = 0.0;
#pragma unroll
    for (int h = 0; h < NGRP; h++) { Sp += (double)g_S[h*NPIX + p]; Sq += (double)g_S[h*NPIX + q]; }
    double avg = (Sp + Sq) * (1.0 / 512.0);
    __shared__ double shl[128];
    __shared__ double sha[128];
    shl[threadIdx.x] = (double)logf((float)avg);
    sha[threadIdx.x] = avg;
    __syncthreads();
    for (int off = 64; off > 0; off >>= 1) {
        if (threadIdx.x < off) {
            shl[threadIdx.x] += shl[threadIdx.x + off];
            sha[threadIdx.x] += sha[threadIdx.x + off];
        }
        __syncthreads();
    }
    if (threadIdx.x == 0) { g_red_log[blockIdx.x] = shl[0]; g_red_avg[blockIdx.x] = sha[0]; }
}

// ---------------- final scalar ----------------
__global__ void final_kernel(float* __restrict__ out) {
    __shared__ double sh[128];
    int t = threadIdx.x;

    sh[t] = (double)(g_lse[t] - g_dist[t*BSZ + t]);
    __syncthreads();
    for (int off = 64; off > 0; off >>= 1) {
        if (t < off) sh[t] += sh[t + off];
        __syncthreads();
    }
    double ce = sh[0] / (double)BSZ;
    __syncthreads();

    sh[t] = g_red_log[t]; __syncthreads();
    for (int off = 64; off > 0; off >>= 1) {
        if (t < off) sh[t] += sh[t + off];
        __syncthreads();
    }
    double slog = sh[0];
    __syncthreads();

    sh[t] = g_red_avg[t]; __syncthreads();
    for (int off = 64; off > 0; off >>= 1) {
        if (t < off) sh[t] += sh[t + off];
        __syncthreads();
    }
    double savg = sh[0];

    if (t == 0) {
        double r = slog / (double)NPIX - log(savg / (double)NPIX);
        out[0] = (float)(ce - 0.1 * r);
    }
}

// ---------------- launch (serial; overlap reverted — proven negative) ----------------
// Order: fft, reduce, dot, stats, dist, final. Legal DAG (stats needs only
// reduce; dot independent). 4th launch = psd_stats so next profile verifies
// the NGRP fix directly.
extern "C" void kernel_launch(void* const* d_in, const int* in_sizes, int n_in,
                              void* d_out, int out_size) {
    const float* x1 = (const float*)d_in[0];
    const float* x2 = (const float*)d_in[1];
    float* out = (float*)d_out;

    const int smem = 2 * 128 * PITCHF * (int)sizeof(float);   // 132096 B
    cudaFuncSetAttribute(fft_psd_kernel, cudaFuncAttributeMaxDynamicSharedMemorySize, smem);

    fft_psd_kernel<<<NPACK, 512, smem>>>(x1, x2);
    psd_reduce_kernel<<<dim3(8, NGRP), 256>>>();
    dot_kernel<<<dim3(2, 1, GK), 256>>>(x1, x2);
    psd_stats_kernel<<<128, 128>>>();
    dist_lse_kernel<<<BSZ, 512>>>();
    final_kernel<<<1, 128>>>(out);
}